// round 4
// baseline (speedup 1.0000x reference)
#include <cuda_runtime.h>
#include <cuda_fp16.h>
#include <cstdint>

// Problem sizes (fixed by the dataset). All tensors are float32 on the wire
// (the harness converts the reference's fp16 arrays to f32).
static constexpr int M = 128;
static constexpr int K = 4096;
static constexpr int N = 11008;

static constexpr int BM = 128;
static constexpr int BN = 128;     // 86 CTAs exactly, single wave
static constexpr int BK = 64;
static constexpr int STAGES = 4;
static constexpr int ITERS = K / BK;   // 64

static constexpr int A_BYTES = BM * BK * 2;           // 16384 (f16 in smem)
static constexpr int B_BYTES = BK * BN * 2;           // 16384 (f16 in smem)
static constexpr int STAGE_BYTES = A_BYTES + B_BYTES; // 32768
static constexpr int SMEM_TOTAL = STAGES * STAGE_BYTES; // 131072

// masked-x scratch in fp16 (device global: no allocations allowed)
__device__ __half g_xm[M * K];

// ---------------------------------------------------------------------------
// Kernel 1: per-(16x64) block mean|x| threshold; write masked x as fp16
// ---------------------------------------------------------------------------
__global__ void mask_kernel(const float* __restrict__ x) {
    __shared__ float warp_part[4];
    __shared__ int flag;
    const int kb = blockIdx.x;      // 0..63
    const int mb = blockIdx.y;      // 0..7
    const int tid = threadIdx.x;    // 128 threads
    const int r  = tid >> 3;        // 0..15 row within block
    const int cg = tid & 7;         // 0..7 col-group (8 floats each)
    const float* p = x + (size_t)(mb * 16 + r) * K + kb * 64 + cg * 8;

    float4 v0 = *reinterpret_cast<const float4*>(p);
    float4 v1 = *reinterpret_cast<const float4*>(p + 4);
    float s = fabsf(v0.x) + fabsf(v0.y) + fabsf(v0.z) + fabsf(v0.w)
            + fabsf(v1.x) + fabsf(v1.y) + fabsf(v1.z) + fabsf(v1.w);
#pragma unroll
    for (int o = 16; o; o >>= 1) s += __shfl_xor_sync(0xffffffffu, s, o);
    if ((tid & 31) == 0) warp_part[tid >> 5] = s;
    __syncthreads();
    if (tid == 0) {
        float t = warp_part[0] + warp_part[1] + warp_part[2] + warp_part[3];
        flag = (t * (1.0f / 1024.0f)) > 0.8f ? 1 : 0;
    }
    __syncthreads();

    uint4 outv;
    if (flag) {
        __half2 h0 = __floats2half2_rn(v0.x, v0.y);
        __half2 h1 = __floats2half2_rn(v0.z, v0.w);
        __half2 h2 = __floats2half2_rn(v1.x, v1.y);
        __half2 h3 = __floats2half2_rn(v1.z, v1.w);
        outv.x = *reinterpret_cast<uint32_t*>(&h0);
        outv.y = *reinterpret_cast<uint32_t*>(&h1);
        outv.z = *reinterpret_cast<uint32_t*>(&h2);
        outv.w = *reinterpret_cast<uint32_t*>(&h3);
    } else {
        outv = make_uint4(0u, 0u, 0u, 0u);
    }
    *reinterpret_cast<uint4*>(g_xm + (size_t)(mb * 16 + r) * K + kb * 64 + cg * 8) = outv;
}

// ---------------------------------------------------------------------------
// PTX helpers (non-'a' features only: cp.async sm_80, ldmatrix sm_75, mma sm_80)
// ---------------------------------------------------------------------------
__device__ __forceinline__ uint32_t smem_u32(const void* p) {
    uint32_t a;
    asm("{ .reg .u64 t; cvta.to.shared.u64 t, %1; cvt.u32.u64 %0, t; }" : "=r"(a) : "l"(p));
    return a;
}
__device__ __forceinline__ void cp_async16(uint32_t dst, const void* src) {
    asm volatile("cp.async.cg.shared.global [%0], [%1], 16;" :: "r"(dst), "l"(src) : "memory");
}
__device__ __forceinline__ void cp_commit() {
    asm volatile("cp.async.commit_group;" ::: "memory");
}
template <int NN>
__device__ __forceinline__ void cp_wait() {
    asm volatile("cp.async.wait_group %0;" :: "n"(NN) : "memory");
}
__device__ __forceinline__ void ldsm_x4(uint32_t (&r)[4], uint32_t addr) {
    asm volatile("ldmatrix.sync.aligned.m8n8.x4.shared.b16 {%0,%1,%2,%3}, [%4];"
                 : "=r"(r[0]), "=r"(r[1]), "=r"(r[2]), "=r"(r[3]) : "r"(addr));
}
__device__ __forceinline__ void ldsm_x4_t(uint32_t (&r)[4], uint32_t addr) {
    asm volatile("ldmatrix.sync.aligned.m8n8.x4.trans.shared.b16 {%0,%1,%2,%3}, [%4];"
                 : "=r"(r[0]), "=r"(r[1]), "=r"(r[2]), "=r"(r[3]) : "r"(addr));
}
__device__ __forceinline__ void mma16816(float (&d)[4], const uint32_t (&a)[4],
                                         uint32_t b0, uint32_t b1) {
    asm volatile(
        "mma.sync.aligned.m16n8k16.row.col.f32.f16.f16.f32 "
        "{%0,%1,%2,%3}, {%4,%5,%6,%7}, {%8,%9}, {%0,%1,%2,%3};"
        : "+f"(d[0]), "+f"(d[1]), "+f"(d[2]), "+f"(d[3])
        : "r"(a[0]), "r"(a[1]), "r"(a[2]), "r"(a[3]), "r"(b0), "r"(b1));
}
__device__ __forceinline__ uint32_t pack_h2(float lo, float hi) {
    __half2 h = __floats2half2_rn(lo, hi);
    return *reinterpret_cast<uint32_t*>(&h);
}

// ---------------------------------------------------------------------------
// Kernel 2: warp-specialized pipelined GEMM  out[128, 11008] = xm @ W + bias
//   256 threads: warps 0-3 consume (2x2 x 64x64 tiles, HMMA f32-acc),
//   warps 4-7 produce (A: cp.async f16 from g_xm; B: LDG f32 -> f16 STS,
//   software-pipelined one iteration ahead).
// ---------------------------------------------------------------------------
__global__ void __launch_bounds__(256, 1)
gemm_kernel(const float* __restrict__ w,
            const float* __restrict__ bias,
            float* __restrict__ out) {
    extern __shared__ char smem[];
    const uint32_t sb = smem_u32(smem);
    const int tid = threadIdx.x;
    const int wid = tid >> 5;
    const int lane = tid & 31;
    const int n_cta = blockIdx.x * BN;
    const bool producer = (wid >= 4);

    if (producer) {
        // ---------------- producer setup ----------------
        const int ptid = tid - 128;          // 0..127
        // A tile: [128 rows][64 halves] = 128B rows, 8x16B chunks, chunk ^= (row&7)
        const int a_row = ptid >> 3;         // 0..15, +16*i
        const int a_chk = ptid & 7;
        const __half* gA = g_xm + (size_t)a_row * K + a_chk * 8;
        const uint32_t sA_st = sb + a_row * 128 + ((a_chk ^ (a_row & 7)) << 4);
        // B tile: [64 k-rows][128 halves] = 256B rows, 16x16B chunks, chunk ^= 2*(krow&7)
        const int b_row = ptid >> 4;         // 0..7, +8*i
        const int b_chk = ptid & 15;
        const float* gB = w + (size_t)b_row * N + n_cta + b_chk * 8;
        const uint32_t sB_st = sb + A_BYTES + b_row * 256 + ((b_chk ^ ((b_row & 7) << 1)) << 4);

        float4 bbuf[16];                     // staged f32 B data for one stage

        auto load_A = [&](int stage, int k0) {
#pragma unroll
            for (int i = 0; i < 8; i++)
                cp_async16(sA_st + stage * STAGE_BYTES + i * (16 * 128),
                           gA + k0 + (size_t)i * 16 * K);
        };
        auto ldg_B = [&](int k0) {
#pragma unroll
            for (int i = 0; i < 8; i++) {
                const float* src = gB + (size_t)(k0 + i * 8) * N;
                bbuf[2 * i]     = *reinterpret_cast<const float4*>(src);
                bbuf[2 * i + 1] = *reinterpret_cast<const float4*>(src + 4);
            }
        };
        auto sts_B = [&](int stage) {
#pragma unroll
            for (int i = 0; i < 8; i++) {
                uint4 u;
                u.x = pack_h2(bbuf[2 * i].x,     bbuf[2 * i].y);
                u.y = pack_h2(bbuf[2 * i].z,     bbuf[2 * i].w);
                u.z = pack_h2(bbuf[2 * i + 1].x, bbuf[2 * i + 1].y);
                u.w = pack_h2(bbuf[2 * i + 1].z, bbuf[2 * i + 1].w);
                *reinterpret_cast<uint4*>(
                    smem + (sB_st - sb) + stage * STAGE_BYTES + i * (8 * 256)) = u;
            }
        };

        // ---------------- prologue: stages 0..2 ----------------
#pragma unroll
        for (int s = 0; s < STAGES - 1; s++) { load_A(s, s * BK); cp_commit(); }
        ldg_B(0 * BK); sts_B(0);
        ldg_B(1 * BK); sts_B(1);
        ldg_B(2 * BK);                        // stage 2 stays in bbuf

        // ---------------- main loop ----------------
        for (int it = 0; it < ITERS; ++it) {
            cp_wait<STAGES - 2>();            // A of stage `it` arrived
            __syncthreads();                  // publish stage `it` to consumers
            if (it + 3 < ITERS) load_A((it + 3) & (STAGES - 1), (it + 3) * BK);
            cp_commit();
            if (it + 2 < ITERS) sts_B((it + 2) & (STAGES - 1));
            if (it + 3 < ITERS) ldg_B((it + 3) * BK);
        }
        return;                               // producers exit (no more barriers)
    }

    // ---------------- consumer setup ----------------
    const int wr = wid >> 1;                  // 0/1 -> m offset
    const int wc = wid & 1;                   // 0/1 -> n offset
    const int m_w = wr * 64;
    const int n_w = wc * 64;

    float acc[4][4][4];                       // first n8 of each n16 group
    float acc2[4][4][4];                      // second n8
#pragma unroll
    for (int a = 0; a < 4; a++)
#pragma unroll
        for (int b = 0; b < 4; b++)
#pragma unroll
            for (int c = 0; c < 4; c++) { acc[a][b][c] = 0.f; acc2[a][b][c] = 0.f; }

    const int a_r = m_w + (lane & 15);        // ldmatrix A row
    const int a_c_hi = lane >> 4;             // k-chunk select
    const int b_k_lo = ((lane >> 3) & 1) * 8 + (lane & 7);  // ldmatrix B k row
    const int b_c_hi = lane >> 4;             // n-chunk select

    for (int it = 0; it < ITERS; ++it) {
        __syncthreads();                      // stage `it` published
        const uint32_t stA = sb + (it & (STAGES - 1)) * STAGE_BYTES;
        const uint32_t stB = stA + A_BYTES;

#pragma unroll
        for (int ks = 0; ks < 4; ++ks) {
            uint32_t afr[4][4];
#pragma unroll
            for (int im = 0; im < 4; ++im) {
                const int row = a_r + im * 16;
                const int chk = (2 * ks + a_c_hi) ^ (row & 7);
                ldsm_x4(afr[im], stA + row * 128 + (chk << 4));
            }
#pragma unroll
            for (int in2 = 0; in2 < 4; ++in2) {
                uint32_t bfr[4];
                const int krow = ks * 16 + b_k_lo;
                const int chk = ((n_w >> 3) + 2 * in2 + b_c_hi) ^ ((krow & 7) << 1);
                ldsm_x4_t(bfr, stB + krow * 256 + (chk << 4));
#pragma unroll
                for (int im = 0; im < 4; ++im) {
                    mma16816(acc[im][in2], afr[im], bfr[0], bfr[1]);
                    mma16816(acc2[im][in2], afr[im], bfr[2], bfr[3]);
                }
            }
        }
    }

    // ---------------- epilogue: +bias, f32 store ----------------
    const int g = lane >> 2;
    const int t = lane & 3;
#pragma unroll
    for (int im = 0; im < 4; ++im) {
        const int m0 = m_w + im * 16 + g;
#pragma unroll
        for (int in2 = 0; in2 < 4; ++in2) {
            const int n0 = n_cta + n_w + in2 * 16 + 2 * t;
            const float2 bz0 = *reinterpret_cast<const float2*>(bias + n0);
            const float2 bz1 = *reinterpret_cast<const float2*>(bias + n0 + 8);
            float2* p0 = reinterpret_cast<float2*>(out + (size_t)m0 * N + n0);
            float2* p1 = reinterpret_cast<float2*>(out + (size_t)(m0 + 8) * N + n0);
            p0[0] = make_float2(acc[im][in2][0] + bz0.x, acc[im][in2][1] + bz0.y);
            p1[0] = make_float2(acc[im][in2][2] + bz0.x, acc[im][in2][3] + bz0.y);
            p0[4] = make_float2(acc2[im][in2][0] + bz1.x, acc2[im][in2][1] + bz1.y);
            p1[4] = make_float2(acc2[im][in2][2] + bz1.x, acc2[im][in2][3] + bz1.y);
        }
    }
}

// ---------------------------------------------------------------------------
// Host launch
// ---------------------------------------------------------------------------
extern "C" void kernel_launch(void* const* d_in, const int* in_sizes, int n_in,
                              void* d_out, int out_size) {
    (void)in_sizes; (void)n_in; (void)out_size;
    const float* x    = (const float*)d_in[0];
    const float* w    = (const float*)d_in[1];
    const float* bias = (const float*)d_in[2];
    float* out        = (float*)d_out;

    mask_kernel<<<dim3(K / 64, M / 16), 128>>>(x);

    cudaFuncSetAttribute(gemm_kernel, cudaFuncAttributeMaxDynamicSharedMemorySize,
                         SMEM_TOTAL);
    gemm_kernel<<<N / BN, 256, SMEM_TOTAL>>>(w, bias, out);
}